// round 12
// baseline (speedup 1.0000x reference)
#include <cuda_runtime.h>
#include <cuda_fp16.h>
#include <cstdint>

// GraphConv SpMM: COO -> fixed-capacity row bins -> warp-per-row SpMM over an
// fp16-compressed, L2-resident embedding table.
//   out[row[i], :] += vals[i] * ego[col[i], :]   for i in [0, NNZ), D = 128
//
// 2 launches:
//   prep_kernel : fused {fp32->fp16 table convert} || {bin scatter} (striped blocks)
//   spmm_kernel : pair-gather SpMM + overflow fixup + self-reset of all scratch state
//
// Scratch state (cursors, over_count, done) is zero at static init and restored
// to zero by spmm_kernel every call -> deterministic across graph replays.

#define EMBED_DIM 128
#define NMAX      200000
#define CAP       96          // Poisson(32) rows; P(overflow) ~ 1e-18/row
#define OVER_CAP  65536

__device__ unsigned long long g_bins[(size_t)NMAX * CAP + 4]; // +pad for uint4 tail read
__device__ uint4              g_ego_h4[(size_t)NMAX * 16];    // fp16 table: 16B x 16 per row
__device__ int                g_cursor[NMAX];                 // self-reset by spmm
__device__ int                g_over_count;                   // self-reset by spmm ticket
__device__ int                g_done;                         // ticket counter
__device__ int                g_over_row[OVER_CAP];
__device__ unsigned long long g_over_pk[OVER_CAP];

// ---------------------------------------------- 1: fused convert || scatter
// Blocks with (bid & 15) == 15 convert the table (grid-stride); the rest scatter.
__global__ __launch_bounds__(256) void prep_kernel(
    const float4* __restrict__ ego4,
    const float* __restrict__ vals,
    const int* __restrict__ row_idx,
    const int* __restrict__ col_idx,
    int nnz, int n_vec)               // n_vec = n * 16 (uint4 per row)
{
    unsigned int b = blockIdx.x;
    if ((b & 15u) == 15u) {
        // ---- convert role: fp32 -> fp16 table ----
        int cid = b >> 4;
        long long stride = (long long)(gridDim.x >> 4) * blockDim.x;
        for (long long i = (long long)cid * blockDim.x + threadIdx.x; i < n_vec; i += stride) {
            float4 f0 = __ldcs(ego4 + 2 * i);        // stream reads (table read once as fp32)
            float4 f1 = __ldcs(ego4 + 2 * i + 1);
            __half2 h0 = __floats2half2_rn(f0.x, f0.y);
            __half2 h1 = __floats2half2_rn(f0.z, f0.w);
            __half2 h2 = __floats2half2_rn(f1.x, f1.y);
            __half2 h3 = __floats2half2_rn(f1.z, f1.w);
            uint4 u;
            u.x = *reinterpret_cast<unsigned int*>(&h0);
            u.y = *reinterpret_cast<unsigned int*>(&h1);
            u.z = *reinterpret_cast<unsigned int*>(&h2);
            u.w = *reinterpret_cast<unsigned int*>(&h3);
            g_ego_h4[i] = u;                          // resident store: hot table
        }
    } else {
        // ---- scatter role: bin (val, col) by row ----
        int sid = (int)(b - (b >> 4));
        long long stride = (long long)(gridDim.x - (gridDim.x >> 4)) * blockDim.x;
        for (long long i = (long long)sid * blockDim.x + threadIdx.x; i < nnz; i += stride) {
            int r = __ldcs(row_idx + i);
            int c = __ldcs(col_idx + i);
            unsigned int vb = __float_as_uint(__ldcs(vals + i));
            unsigned long long pk = ((unsigned long long)vb << 32) | (unsigned int)c;
            int pos = atomicAdd(&g_cursor[r], 1);
            if (pos < CAP) {
                asm volatile("st.global.cs.u64 [%0], %1;"
                             :: "l"(g_bins + (size_t)r * CAP + pos), "l"(pk) : "memory");
            } else {
                int k = atomicAdd(&g_over_count, 1);
                if (k < OVER_CAP) { g_over_row[k] = r; g_over_pk[k] = pk; }
            }
        }
    }
}

// ---------------------------------------------- 2: SpMM (warp per row, pair-gather)
// Half-warp 0 (lanes 0-15) handles even entries, half-warp 1 odd entries.
// Lane q in [0,16) owns output floats [8q..8q+7]; one LDG.128 per lane covers
// 8 halves of its half-warp's row -> one warp LDG gathers TWO rows.
__global__ __launch_bounds__(256) void spmm_kernel(
    const float4* __restrict__ ego4,   // fp32 table (exact path for overflow only)
    float4* __restrict__ out4,
    int n_rows)
{
    int warp = (blockIdx.x * blockDim.x + threadIdx.x) >> 5;
    int lane = threadIdx.x & 31;
    int sub  = lane >> 4;       // which nnz of the pair
    int q    = lane & 15;       // position within the row (8 halves)

    if (warp < n_rows) {
        int cnt = g_cursor[warp];
        __syncwarp();
        if (lane == 0) g_cursor[warp] = 0;            // self-reset for next call
        int cnt_c = min(cnt, CAP);

        const uint4* bin4 = reinterpret_cast<const uint4*>(g_bins + (size_t)warp * CAP);

        float a0=0.f,a1=0.f,a2=0.f,a3=0.f,a4=0.f,a5=0.f,a6=0.f,a7=0.f;

        int npair = cnt_c >> 1;
        int p = 0;
        // 2 pairs (4 nnz) in flight: 2 bin LDG.128 + 2 gather LDG.128
        for (; p + 2 <= npair; p += 2) {
            uint4 e0 = __ldcs(bin4 + p);              // entries 2p, 2p+1
            uint4 e1 = __ldcs(bin4 + p + 1);          // entries 2p+2, 2p+3
            unsigned int c0 = sub ? e0.z : e0.x;
            float        v0 = __uint_as_float(sub ? e0.w : e0.y);
            unsigned int c1 = sub ? e1.z : e1.x;
            float        v1 = __uint_as_float(sub ? e1.w : e1.y);
            uint4 u0 = __ldg(g_ego_h4 + (size_t)c0 * 16 + q);
            uint4 u1 = __ldg(g_ego_h4 + (size_t)c1 * 16 + q);

            float2 f;
            f = __half22float2(*reinterpret_cast<__half2*>(&u0.x)); a0 += v0*f.x; a1 += v0*f.y;
            f = __half22float2(*reinterpret_cast<__half2*>(&u0.y)); a2 += v0*f.x; a3 += v0*f.y;
            f = __half22float2(*reinterpret_cast<__half2*>(&u0.z)); a4 += v0*f.x; a5 += v0*f.y;
            f = __half22float2(*reinterpret_cast<__half2*>(&u0.w)); a6 += v0*f.x; a7 += v0*f.y;
            f = __half22float2(*reinterpret_cast<__half2*>(&u1.x)); a0 += v1*f.x; a1 += v1*f.y;
            f = __half22float2(*reinterpret_cast<__half2*>(&u1.y)); a2 += v1*f.x; a3 += v1*f.y;
            f = __half22float2(*reinterpret_cast<__half2*>(&u1.z)); a4 += v1*f.x; a5 += v1*f.y;
            f = __half22float2(*reinterpret_cast<__half2*>(&u1.w)); a6 += v1*f.x; a7 += v1*f.y;
        }
        for (; p < npair; p++) {                      // leftover full pair
            uint4 e0 = __ldcs(bin4 + p);
            unsigned int c0 = sub ? e0.z : e0.x;
            float        v0 = __uint_as_float(sub ? e0.w : e0.y);
            uint4 u0 = __ldg(g_ego_h4 + (size_t)c0 * 16 + q);
            float2 f;
            f = __half22float2(*reinterpret_cast<__half2*>(&u0.x)); a0 += v0*f.x; a1 += v0*f.y;
            f = __half22float2(*reinterpret_cast<__half2*>(&u0.y)); a2 += v0*f.x; a3 += v0*f.y;
            f = __half22float2(*reinterpret_cast<__half2*>(&u0.z)); a4 += v0*f.x; a5 += v0*f.y;
            f = __half22float2(*reinterpret_cast<__half2*>(&u0.w)); a6 += v0*f.x; a7 += v0*f.y;
        }
        if (cnt_c & 1) {                              // odd tail: sub 1 contributes 0
            uint4 e0 = __ldcs(bin4 + npair);          // entries cnt-1, cnt (pad-safe)
            unsigned int c0 = sub ? 0u   : e0.x;
            float        v0 = sub ? 0.f  : __uint_as_float(e0.y);
            uint4 u0 = __ldg(g_ego_h4 + (size_t)c0 * 16 + q);
            float2 f;
            f = __half22float2(*reinterpret_cast<__half2*>(&u0.x)); a0 += v0*f.x; a1 += v0*f.y;
            f = __half22float2(*reinterpret_cast<__half2*>(&u0.y)); a2 += v0*f.x; a3 += v0*f.y;
            f = __half22float2(*reinterpret_cast<__half2*>(&u0.z)); a4 += v0*f.x; a5 += v0*f.y;
            f = __half22float2(*reinterpret_cast<__half2*>(&u0.w)); a6 += v0*f.x; a7 += v0*f.y;
        }

        // combine the two half-warps: lane q += lane q+16
        a0 += __shfl_down_sync(0xFFFFFFFFu, a0, 16);
        a1 += __shfl_down_sync(0xFFFFFFFFu, a1, 16);
        a2 += __shfl_down_sync(0xFFFFFFFFu, a2, 16);
        a3 += __shfl_down_sync(0xFFFFFFFFu, a3, 16);
        a4 += __shfl_down_sync(0xFFFFFFFFu, a4, 16);
        a5 += __shfl_down_sync(0xFFFFFFFFu, a5, 16);
        a6 += __shfl_down_sync(0xFFFFFFFFu, a6, 16);
        a7 += __shfl_down_sync(0xFFFFFFFFu, a7, 16);

        if (sub == 0) {                               // lanes 0-15 store 32B each
            float4 o0 = make_float4(a0, a1, a2, a3);
            float4 o1 = make_float4(a4, a5, a6, a7);
            __stcs(out4 + (size_t)warp * 32 + 2 * q,     o0);
            __stcs(out4 + (size_t)warp * 32 + 2 * q + 1, o1);
        }

        // overflow fixup (normally tot == 0): exact fp32 path, owning warp only
        int tot = g_over_count;
        if (tot > 0) {
            tot = min(tot, OVER_CAP);
            for (int k = 0; k < tot; k++) {
                if (g_over_row[k] == warp) {
                    unsigned long long pk = g_over_pk[k];
                    int   c = (int)(unsigned int)pk;
                    float v = __uint_as_float((unsigned int)(pk >> 32));
                    float4 e = __ldg(ego4 + (size_t)c * 32 + lane);
                    float* dst = reinterpret_cast<float*>(out4) + (size_t)warp * EMBED_DIM + lane * 4;
                    asm volatile("red.global.add.v4.f32 [%0], {%1, %2, %3, %4};"
                                 :: "l"(dst), "f"(v*e.x), "f"(v*e.y), "f"(v*e.z), "f"(v*e.w)
                                 : "memory");
                }
            }
        }
    }

    // last-block ticket resets overflow state for the next call
    __syncthreads();
    if (threadIdx.x == 0) {
        int t = atomicAdd(&g_done, 1);
        if (t == (int)gridDim.x - 1) {
            atomicExch(&g_over_count, 0);
            atomicExch(&g_done, 0);
        }
    }
}

extern "C" void kernel_launch(void* const* d_in, const int* in_sizes, int n_in,
                              void* d_out, int out_size) {
    const float* ego  = (const float*)d_in[0];
    const float* vals = (const float*)d_in[1];
    const int* row    = (const int*)d_in[2];
    const int* col    = (const int*)d_in[3];
    float* out        = (float*)d_out;

    int nnz   = in_sizes[1];               // 6400000
    int n     = out_size / EMBED_DIM;      // 200000
    int n_vec = n * 16;                    // uint4 per table

    // 25600 blocks: 1600 convert (every 16th) interleaved with 24000 scatter
    prep_kernel<<<25600, 256>>>((const float4*)ego, vals, row, col, nnz, n_vec);

    long long total_threads = (long long)n * 32;   // warp per row
    int blocks = (int)((total_threads + 255) / 256);
    spmm_kernel<<<blocks, 256>>>((const float4*)ego, (float4*)out, n);
}